// round 14
// baseline (speedup 1.0000x reference)
#include <cuda_runtime.h>
#include <cuda_bf16.h>
#include <cuda_fp16.h>
#include <cstdint>
#include <math.h>

#define BSZ   2048
#define NTOT  4096
#define DDIM  256
#define NTILE 32
#define NTRI  528            // upper-triangular 128x128 tiles
#define BKS   64             // K per stage
#define NKT   4              // DDIM / BKS
#define STG   16384          // 128 rows * 128 B per stage buffer
#define OFF_A 0
#define OFF_B (2 * STG)
#define SMEM_TOTAL (4 * STG)
#define NTHR  512
#define L2E2  2.885390081777927f   // 2*log2(e)

// Scratch (device globals; no allocation allowed)
__device__ uint4  g_znb4[NTOT * DDIM / 8];
__device__ float  g_rowsum[NTOT];
__device__ float  g_pos[NTOT];
__device__ unsigned g_done = 0;

// ---------------------------------------------------------------------------
// Kernel 1: L2-normalize rows -> bf16; zero accumulators + completion counter
// ---------------------------------------------------------------------------
__global__ __launch_bounds__(256) void nt_normalize(const float* __restrict__ zi,
                                                    const float* __restrict__ zj) {
    int row  = (blockIdx.x * blockDim.x + threadIdx.x) >> 5;
    int lane = threadIdx.x & 31;
    if (blockIdx.x == 0 && threadIdx.x == 0) g_done = 0u;
    if (row >= NTOT) return;

    const float* src = (row < BSZ) ? (zi + (size_t)row * DDIM)
                                   : (zj + (size_t)(row - BSZ) * DDIM);
    const float4* s4 = (const float4*)src;
    float4 a = s4[lane];
    float4 b = s4[lane + 32];

    float ss = a.x*a.x + a.y*a.y + a.z*a.z + a.w*a.w
             + b.x*b.x + b.y*b.y + b.z*b.z + b.w*b.w;
#pragma unroll
    for (int o = 16; o; o >>= 1) ss += __shfl_xor_sync(0xFFFFFFFFu, ss, o);

    float inv = 1.0f / fmaxf(sqrtf(ss), 1e-8f);

    __nv_bfloat162* d2 = (__nv_bfloat162*)((__nv_bfloat16*)g_znb4 + (size_t)row * DDIM);
    d2[2*lane]          = __nv_bfloat162(__float2bfloat16(a.x*inv), __float2bfloat16(a.y*inv));
    d2[2*lane + 1]      = __nv_bfloat162(__float2bfloat16(a.z*inv), __float2bfloat16(a.w*inv));
    d2[64 + 2*lane]     = __nv_bfloat162(__float2bfloat16(b.x*inv), __float2bfloat16(b.y*inv));
    d2[64 + 2*lane + 1] = __nv_bfloat162(__float2bfloat16(b.z*inv), __float2bfloat16(b.w*inv));

    if (lane == 0) g_rowsum[row] = 0.0f;
}

// ---------------------------------------------------------------------------
// Helpers
// ---------------------------------------------------------------------------
__device__ __forceinline__ void cp_async16(uint32_t s, const void* g) {
    asm volatile("cp.async.cg.shared.global [%0], [%1], 16;\n" :: "r"(s), "l"(g));
}
__device__ __forceinline__ void cp_commit() { asm volatile("cp.async.commit_group;\n"); }
__device__ __forceinline__ void cp_wait1()  { asm volatile("cp.async.wait_group 1;\n"); }
__device__ __forceinline__ void cp_wait0()  { asm volatile("cp.async.wait_group 0;\n"); }
__device__ __forceinline__ void ldm_x4(uint32_t addr, uint32_t& r0, uint32_t& r1,
                                       uint32_t& r2, uint32_t& r3) {
    asm volatile("ldmatrix.sync.aligned.m8n8.x4.shared.b16 {%0,%1,%2,%3}, [%4];\n"
                 : "=r"(r0), "=r"(r1), "=r"(r2), "=r"(r3) : "r"(addr));
}
__device__ __forceinline__ void mma16816(float& d0, float& d1, float& d2, float& d3,
                                         uint32_t a0, uint32_t a1, uint32_t a2, uint32_t a3,
                                         uint32_t b0, uint32_t b1) {
    asm volatile("mma.sync.aligned.m16n8k16.row.col.f32.bf16.bf16.f32 "
                 "{%0,%1,%2,%3}, {%4,%5,%6,%7}, {%8,%9}, {%0,%1,%2,%3};\n"
                 : "+f"(d0), "+f"(d1), "+f"(d2), "+f"(d3)
                 : "r"(a0), "r"(a1), "r"(a2), "r"(a3), "r"(b0), "r"(b1));
}
__device__ __forceinline__ uint32_t sw128(uint32_t off) {
    return off ^ ((off >> 3) & 0x70);
}
__device__ __forceinline__ float ex2f(float x) {
    float r;
    asm("ex2.approx.ftz.f32 %0, %1;" : "=f"(r) : "f"(x));
    return r;
}
__device__ __forceinline__ __half2 h2_ex2(__half2 x) {
    uint32_t xi = *reinterpret_cast<uint32_t*>(&x);
    uint32_t ri;
    asm("ex2.approx.f16x2 %0, %1;" : "=r"(ri) : "r"(xi));
    return *reinterpret_cast<__half2*>(&ri);
}

// ---------------------------------------------------------------------------
// Kernel 2: bf16 mma.sync GEMM on upper-triangular tiles.
// 512 threads, 16 warps (4m x 4n). All smem addressing strength-reduced:
// swizzle XOR constant c=(lane&7)<<4 is row/stage invariant; k-step term
// occupies disjoint bits -> addr = base + ((ks*32)^c56).
// ---------------------------------------------------------------------------
__global__ __launch_bounds__(NTHR, 2) void nt_mma(float* __restrict__ out) {
    extern __shared__ __align__(1024) char smem[];
    uint32_t sb;
    asm("{ .reg .u64 t; cvta.to.shared.u64 t, %1; cvt.u32.u64 %0, t; }"
        : "=r"(sb) : "l"((const void*)smem));

    // decode upper-triangular tile index -> (bi, bj), bi <= bj
    int t = blockIdx.x, bi = 0;
    while (t >= NTILE - bi) { t -= NTILE - bi; bi++; }
    const int bj = bi + t;
    const bool diag    = (bi == bj);
    const bool posTile = (bj - bi == 16);
    const int rowBase = bi * 128;
    const int colBase = bj * 128;

    const int tid  = threadIdx.x;
    const int wid  = tid >> 5;
    const int lane = tid & 31;
    const int warp_m = wid & 3;      // 32 rows each
    const int warp_n = wid >> 2;     // 32 cols each

    const char* Zb = (const char*)g_znb4;

    float acc[2][4][4];
#pragma unroll
    for (int mi = 0; mi < 2; mi++)
#pragma unroll
        for (int ni = 0; ni < 4; ni++)
#pragma unroll
            for (int r = 0; r < 4; r++) acc[mi][ni][r] = 0.0f;

    // ---- precomputed loader addresses (4 chunks/thread: A r0, A r0+64, B x2)
    const int lr = tid >> 3;               // 0..63
    const int lc = tid & 7;                // 0..7
    const uint32_t dA0 = sb + OFF_A + sw128((uint32_t)(lr * 128 + lc * 16));
    const uint32_t dA1 = sb + OFF_A + sw128((uint32_t)((lr + 64) * 128 + lc * 16));
    const char* pA = Zb + (size_t)(rowBase + lr) * 512 + lc * 16;
    const char* pB = Zb + (size_t)(colBase + lr) * 512 + lc * 16;

    auto load_stage = [&](int st) {
        const uint32_t sx = (uint32_t)(st & 1) * STG;
        const char* a = pA + st * 128;
        cp_async16(dA0 + sx, a);
        cp_async16(dA1 + sx, a + 32768);
        if (!diag) {
            const char* b = pB + st * 128;
            cp_async16(dA0 + OFF_B + sx, b);
            cp_async16(dA1 + OFF_B + sx, b + 32768);
        }
        cp_commit();
    };

    // ---- precomputed ldmatrix bases
    const uint32_t c   = (uint32_t)(lane & 7) << 4;
    const uint32_t c4  = c & 0x10;
    const uint32_t c56 = c & 0x60;
    const uint32_t bOfs = diag ? (uint32_t)OFF_A : (uint32_t)OFF_B;
    // A: row = warp_m*32 + mi*16 + (lane&15); bit4 term = (lane>>4)*16 ^ c4
    const uint32_t bA0 = sb + OFF_A
        + (uint32_t)((warp_m * 32 + (lane & 15)) * 128)
        + (((uint32_t)(lane >> 4) * 16) ^ c4);
    // B: nrow = warp_n*32 + p*16 + (lane>>4)*8 + (lane&7); bit4 = ((lane>>3)&1)*16 ^ c4
    const uint32_t bB0 = sb + bOfs
        + (uint32_t)((warp_n * 32 + (lane >> 4) * 8 + (lane & 7)) * 128)
        + ((((uint32_t)(lane >> 3) & 1) * 16) ^ c4);

    load_stage(0);

    for (int st = 0; st < NKT; st++) {
        if (st + 1 < NKT) { load_stage(st + 1); cp_wait1(); }
        else              { cp_wait0(); }
        __syncthreads();

        const uint32_t sx = (uint32_t)(st & 1) * STG;
        const uint32_t a0 = bA0 + sx, a1 = a0 + 2048;
        const uint32_t b0 = bB0 + sx, b1 = b0 + 2048;
#pragma unroll
        for (int ks = 0; ks < 4; ks++) {
            const uint32_t kk = ((uint32_t)ks * 32) ^ c56;
            uint32_t a[2][4], b[4][2];
            ldm_x4(a0 + kk, a[0][0], a[0][1], a[0][2], a[0][3]);
            ldm_x4(a1 + kk, a[1][0], a[1][1], a[1][2], a[1][3]);
            ldm_x4(b0 + kk, b[0][0], b[0][1], b[1][0], b[1][1]);
            ldm_x4(b1 + kk, b[2][0], b[2][1], b[3][0], b[3][1]);
#pragma unroll
            for (int mi = 0; mi < 2; mi++)
#pragma unroll
                for (int ni = 0; ni < 4; ni++)
                    mma16816(acc[mi][ni][0], acc[mi][ni][1], acc[mi][ni][2], acc[mi][ni][3],
                             a[mi][0], a[mi][1], a[mi][2], a[mi][3],
                             b[ni][0], b[ni][1]);
        }
        __syncthreads();
    }

    // ---- Epilogue: f16x2 paired exp. e = 2^(a*L2E2 - L2E2) = exp(2a-2)
    const __half2 hM = __float2half2_rn(L2E2);
    const __half2 hB = __float2half2_rn(-L2E2);
    __half2 colsum2[4];
#pragma unroll
    for (int ni = 0; ni < 4; ni++) colsum2[ni] = __float2half2_rn(0.0f);

#pragma unroll
    for (int mi = 0; mi < 2; mi++) {
#pragma unroll
        for (int half = 0; half < 2; half++) {
            int row = rowBase + warp_m * 32 + mi * 16 + half * 8 + (lane >> 2);
            __half2 e2[4];
#pragma unroll
            for (int ni = 0; ni < 4; ni++) {
                __half2 h = __floats2half2_rn(acc[mi][ni][half * 2 + 0],
                                              acc[mi][ni][half * 2 + 1]);
                e2[ni] = h2_ex2(__hfma2(h, hM, hB));
                colsum2[ni] = __hadd2(colsum2[ni], e2[ni]);
            }
            float2 vf = __half22float2(__hadd2(__hadd2(e2[0], e2[1]),
                                               __hadd2(e2[2], e2[3])));
            float s = vf.x + vf.y;

            if (diag) {
#pragma unroll
                for (int ni = 0; ni < 4; ni++)
#pragma unroll
                    for (int cc = 0; cc < 2; cc++) {
                        int col = colBase + warp_n * 32 + ni * 8 + 2 * (lane & 3) + cc;
                        if (col == row)
                            s -= ex2f(fmaf(acc[mi][ni][half * 2 + cc], L2E2, -L2E2));
                    }
            } else if (posTile) {
#pragma unroll
                for (int ni = 0; ni < 4; ni++)
#pragma unroll
                    for (int cc = 0; cc < 2; cc++) {
                        int col = colBase + warp_n * 32 + ni * 8 + 2 * (lane & 3) + cc;
                        if (col == row + BSZ) {
                            float v = acc[mi][ni][half * 2 + cc] * 2.0f;
                            g_pos[row] = v; g_pos[col] = v;
                        }
                    }
            }
            s += __shfl_xor_sync(0xFFFFFFFFu, s, 1);
            s += __shfl_xor_sync(0xFFFFFFFFu, s, 2);
            if ((lane & 3) == 0) atomicAdd(&g_rowsum[row], s);
        }
    }

    if (!diag) {
#pragma unroll
        for (int ni = 0; ni < 4; ni++) {
            float2 cf = __half22float2(colsum2[ni]);
#pragma unroll
            for (int cc = 0; cc < 2; cc++) {
                float s = cc ? cf.y : cf.x;
                s += __shfl_xor_sync(0xFFFFFFFFu, s, 4);
                s += __shfl_xor_sync(0xFFFFFFFFu, s, 8);
                s += __shfl_xor_sync(0xFFFFFFFFu, s, 16);
                if (lane < 4) {
                    int col = colBase + warp_n * 32 + ni * 8 + 2 * lane + cc;
                    atomicAdd(&g_rowsum[col], s);
                }
            }
        }
    }

    // ---- last-CTA finalize
    __threadfence();
    __syncthreads();
    __shared__ unsigned s_last;
    if (tid == 0) s_last = (atomicAdd(&g_done, 1u) == NTRI - 1) ? 1u : 0u;
    __syncthreads();
    if (s_last) {
        __shared__ float red[NTHR];
        float s = 0.0f;
        for (int i = tid; i < NTOT; i += NTHR)
            s += 2.0f + logf(__ldcg(&g_rowsum[i])) - __ldcg(&g_pos[i]);
        red[tid] = s;
        __syncthreads();
#pragma unroll
        for (int o = NTHR / 2; o; o >>= 1) {
            if (tid < o) red[tid] += red[tid + o];
            __syncthreads();
        }
        if (tid == 0) out[0] = red[0] * (1.0f / NTOT);
    }
}

extern "C" void kernel_launch(void* const* d_in, const int* in_sizes, int n_in,
                              void* d_out, int out_size) {
    const float* zi = (const float*)d_in[0];
    const float* zj = (const float*)d_in[1];
    float* out = (float*)d_out;
    (void)in_sizes; (void)n_in; (void)out_size;

    cudaFuncSetAttribute(nt_mma, cudaFuncAttributeMaxDynamicSharedMemorySize, SMEM_TOTAL);

    nt_normalize<<<NTOT / 8, 256>>>(zi, zj);
    nt_mma<<<NTRI, NTHR, SMEM_TOTAL>>>(out);
}

// round 15
// speedup vs baseline: 1.0736x; 1.0736x over previous
#include <cuda_runtime.h>
#include <cuda_bf16.h>
#include <cuda_fp16.h>
#include <cstdint>
#include <math.h>

#define BSZ   2048
#define NTOT  4096
#define DDIM  256
#define NT2   272            // tiles: sum_{bjc=0..15} (2*bjc+2)
#define NKT   4              // K stages (64 each)
#define STG_A 16384
#define STG_B 32768
#define OFF_B 32768          // [A0 16K][A1 16K][B0 32K][B1 32K]
#define SMEM_TOTAL 98304
#define NTHR  512
#define L2E2  2.885390081777927f   // 2*log2(e)

// Scratch (device globals; no allocation allowed)
__device__ uint4  g_znh4[NTOT * DDIM / 8];   // normalized rows, fp16
__device__ float  g_rowsum[NTOT];
__device__ float  g_pos[NTOT];
__device__ unsigned g_done = 0;

// ---------------------------------------------------------------------------
// Kernel 1: L2-normalize rows -> fp16; zero accumulators + completion counter
// ---------------------------------------------------------------------------
__global__ __launch_bounds__(256) void nt_normalize(const float* __restrict__ zi,
                                                    const float* __restrict__ zj) {
    int row  = (blockIdx.x * blockDim.x + threadIdx.x) >> 5;
    int lane = threadIdx.x & 31;
    if (blockIdx.x == 0 && threadIdx.x == 0) g_done = 0u;
    if (row >= NTOT) return;

    const float* src = (row < BSZ) ? (zi + (size_t)row * DDIM)
                                   : (zj + (size_t)(row - BSZ) * DDIM);
    const float4* s4 = (const float4*)src;
    float4 a = s4[lane];
    float4 b = s4[lane + 32];

    float ss = a.x*a.x + a.y*a.y + a.z*a.z + a.w*a.w
             + b.x*b.x + b.y*b.y + b.z*b.z + b.w*b.w;
#pragma unroll
    for (int o = 16; o; o >>= 1) ss += __shfl_xor_sync(0xFFFFFFFFu, ss, o);

    float inv = 1.0f / fmaxf(sqrtf(ss), 1e-8f);

    __half2* d2 = (__half2*)((__half*)g_znh4 + (size_t)row * DDIM);
    d2[2*lane]          = __floats2half2_rn(a.x*inv, a.y*inv);
    d2[2*lane + 1]      = __floats2half2_rn(a.z*inv, a.w*inv);
    d2[64 + 2*lane]     = __floats2half2_rn(b.x*inv, b.y*inv);
    d2[64 + 2*lane + 1] = __floats2half2_rn(b.z*inv, b.w*inv);

    if (lane == 0) g_rowsum[row] = 0.0f;
}

// ---------------------------------------------------------------------------
// Helpers
// ---------------------------------------------------------------------------
__device__ __forceinline__ void cp_async16(uint32_t s, const void* g) {
    asm volatile("cp.async.cg.shared.global [%0], [%1], 16;\n" :: "r"(s), "l"(g));
}
__device__ __forceinline__ void cp_commit() { asm volatile("cp.async.commit_group;\n"); }
__device__ __forceinline__ void cp_wait1()  { asm volatile("cp.async.wait_group 1;\n"); }
__device__ __forceinline__ void cp_wait0()  { asm volatile("cp.async.wait_group 0;\n"); }
__device__ __forceinline__ void ldm_x4(uint32_t addr, uint32_t& r0, uint32_t& r1,
                                       uint32_t& r2, uint32_t& r3) {
    asm volatile("ldmatrix.sync.aligned.m8n8.x4.shared.b16 {%0,%1,%2,%3}, [%4];\n"
                 : "=r"(r0), "=r"(r1), "=r"(r2), "=r"(r3) : "r"(addr));
}
// fp16 inputs, fp16 accumulators (packed f16x2): 2 acc regs per m16n8 tile
__device__ __forceinline__ void mma16816h(uint32_t& d0, uint32_t& d1,
                                          uint32_t a0, uint32_t a1, uint32_t a2, uint32_t a3,
                                          uint32_t b0, uint32_t b1) {
    asm volatile("mma.sync.aligned.m16n8k16.row.col.f16.f16.f16.f16 "
                 "{%0,%1}, {%2,%3,%4,%5}, {%6,%7}, {%0,%1};\n"
                 : "+r"(d0), "+r"(d1)
                 : "r"(a0), "r"(a1), "r"(a2), "r"(a3), "r"(b0), "r"(b1));
}
__device__ __forceinline__ uint32_t sw128(uint32_t off) {
    return off ^ ((off >> 3) & 0x70);
}
__device__ __forceinline__ float ex2f(float x) {
    float r;
    asm("ex2.approx.ftz.f32 %0, %1;" : "=f"(r) : "f"(x));
    return r;
}
__device__ __forceinline__ __half2 h2_ex2(__half2 x) {
    uint32_t xi = *reinterpret_cast<uint32_t*>(&x);
    uint32_t ri;
    asm("ex2.approx.f16x2 %0, %1;" : "=r"(ri) : "r"(xi));
    return *reinterpret_cast<__half2*>(&ri);
}

// ---------------------------------------------------------------------------
// Kernel 2: fp16 mma.sync GEMM, 128x256 tiles covering the upper triangle.
// 512 threads (4m x 4n warps, warp tile 32x64). f16x2 accumulators (32 regs).
// Per-warp specialization: its 64 cols lie in ONE 128-col block ->
// skip (below diag) / diag / pos flags are warp-uniform.
// ---------------------------------------------------------------------------
__global__ __launch_bounds__(NTHR, 2) void nt_mma(float* __restrict__ out) {
    extern __shared__ __align__(1024) char smem[];
    uint32_t sb;
    asm("{ .reg .u64 t; cvta.to.shared.u64 t, %1; cvt.u32.u64 %0, t; }"
        : "=r"(sb) : "l"((const void*)smem));

    // decode tile: for bjc in 0..15, bi in 0..2*bjc+1
    int t = blockIdx.x, bjc = 0;
    while (t >= 2 * bjc + 2) { t -= 2 * bjc + 2; bjc++; }
    const int bi = t;
    const int rowBase    = bi * 128;
    const int colBase256 = bjc * 256;

    const int tid  = threadIdx.x;
    const int wid  = tid >> 5;
    const int lane = tid & 31;
    const int warp_m = wid & 3;      // 32 rows each
    const int warp_n = wid >> 2;     // 64 cols each

    const int colBlock = 2 * bjc + (warp_n >> 1);   // this warp's 128-col block
    const bool skipW = (colBlock < bi);
    const bool diagW = (colBlock == bi);
    const bool posW  = (colBlock == bi + 16);

    const char* Zb = (const char*)g_znh4;

    uint32_t acc[2][8][2];           // f16x2 accumulators
#pragma unroll
    for (int mi = 0; mi < 2; mi++)
#pragma unroll
        for (int ni = 0; ni < 8; ni++) { acc[mi][ni][0] = 0u; acc[mi][ni][1] = 0u; }

    // loader: A 1024 chunks (2/thr), B 2048 chunks (4/thr), 16B each
    const int lr = tid >> 3, lc = tid & 7;
    const uint32_t sw0 = sw128((uint32_t)(lr * 128 + lc * 16));
    auto load_stage = [&](int st) {
        const uint32_t sxA = sb + (uint32_t)(st & 1) * STG_A + sw0;
        const uint32_t sxB = sb + OFF_B + (uint32_t)(st & 1) * STG_B + sw0;
        const char* a = Zb + (size_t)(rowBase + lr) * 512 + lc * 16 + st * 128;
        const char* b = Zb + (size_t)(colBase256 + lr) * 512 + lc * 16 + st * 128;
        cp_async16(sxA,         a);
        cp_async16(sxA + 8192,  a + 32768);
        cp_async16(sxB,          b);
        cp_async16(sxB + 8192,   b + 32768);
        cp_async16(sxB + 16384,  b + 65536);
        cp_async16(sxB + 24576,  b + 98304);
        cp_commit();
    };

    // ldmatrix bases (strength-reduced swizzle, verified rounds 13/14)
    const uint32_t c   = (uint32_t)(lane & 7) << 4;
    const uint32_t c4  = c & 0x10;
    const uint32_t c56 = c & 0x60;
    const uint32_t bA0 = sb
        + (uint32_t)((warp_m * 32 + (lane & 15)) * 128)
        + (((uint32_t)(lane >> 4) * 16) ^ c4);
    const uint32_t bB0 = sb + OFF_B
        + (uint32_t)((warp_n * 64 + (lane >> 4) * 8 + (lane & 7)) * 128)
        + ((((uint32_t)(lane >> 3) & 1) * 16) ^ c4);

    load_stage(0);

    for (int st = 0; st < NKT; st++) {
        if (st + 1 < NKT) { load_stage(st + 1); cp_wait1(); }
        else              { cp_wait0(); }
        __syncthreads();

        if (!skipW) {
            const uint32_t a0 = bA0 + (uint32_t)(st & 1) * STG_A;
            const uint32_t b0 = bB0 + (uint32_t)(st & 1) * STG_B;
#pragma unroll
            for (int ks = 0; ks < 4; ks++) {
                const uint32_t kk = ((uint32_t)ks * 32) ^ c56;
                uint32_t a[2][4];
                ldm_x4(a0 + kk,        a[0][0], a[0][1], a[0][2], a[0][3]);
                ldm_x4(a0 + 2048 + kk, a[1][0], a[1][1], a[1][2], a[1][3]);
#pragma unroll
                for (int p = 0; p < 4; p++) {
                    uint32_t b00, b01, b10, b11;
                    ldm_x4(b0 + (uint32_t)p * 2048 + kk, b00, b01, b10, b11);
#pragma unroll
                    for (int mi = 0; mi < 2; mi++) {
                        mma16816h(acc[mi][2*p][0],   acc[mi][2*p][1],
                                  a[mi][0], a[mi][1], a[mi][2], a[mi][3], b00, b01);
                        mma16816h(acc[mi][2*p+1][0], acc[mi][2*p+1][1],
                                  a[mi][0], a[mi][1], a[mi][2], a[mi][3], b10, b11);
                    }
                }
            }
        }
        __syncthreads();
    }

    // ---- Epilogue: e = 2^(a*L2E2 - L2E2) = exp(2a-2), directly on f16 acc.
    if (!skipW) {
        const int wc = colBase256 + warp_n * 64;
        const __half2 hM = __float2half2_rn(L2E2);
        const __half2 hB = __float2half2_rn(-L2E2);
        __half2 colsum2[8];
#pragma unroll
        for (int ni = 0; ni < 8; ni++) colsum2[ni] = __float2half2_rn(0.0f);

#pragma unroll
        for (int mi = 0; mi < 2; mi++) {
#pragma unroll
            for (int half = 0; half < 2; half++) {
                int row = rowBase + warp_m * 32 + mi * 16 + half * 8 + (lane >> 2);
                __half2 e2[8];
#pragma unroll
                for (int ni = 0; ni < 8; ni++) {
                    __half2 av = *reinterpret_cast<__half2*>(&acc[mi][ni][half]);
                    e2[ni] = h2_ex2(__hfma2(av, hM, hB));
                    colsum2[ni] = __hadd2(colsum2[ni], e2[ni]);
                }
                __half2 t0 = __hadd2(__hadd2(e2[0], e2[1]), __hadd2(e2[2], e2[3]));
                __half2 t1 = __hadd2(__hadd2(e2[4], e2[5]), __hadd2(e2[6], e2[7]));
                float2 vf = __half22float2(__hadd2(t0, t1));
                float s = vf.x + vf.y;

                if (diagW) {
                    // remove self term (recompute at f32 accuracy of the f16 acc value)
#pragma unroll
                    for (int ni = 0; ni < 8; ni++)
#pragma unroll
                        for (int cc = 0; cc < 2; cc++) {
                            int col = wc + ni * 8 + 2 * (lane & 3) + cc;
                            if (col == row) {
                                __half2 av = *reinterpret_cast<__half2*>(&acc[mi][ni][half]);
                                float v = cc ? __half2float(__high2half(av))
                                             : __half2float(__low2half(av));
                                s -= ex2f(fmaf(v, L2E2, -L2E2));
                            }
                        }
                } else if (posW) {
#pragma unroll
                    for (int ni = 0; ni < 8; ni++)
#pragma unroll
                        for (int cc = 0; cc < 2; cc++) {
                            int col = wc + ni * 8 + 2 * (lane & 3) + cc;
                            if (col == row + BSZ) {
                                __half2 av = *reinterpret_cast<__half2*>(&acc[mi][ni][half]);
                                float v = 2.0f * (cc ? __half2float(__high2half(av))
                                                     : __half2float(__low2half(av)));
                                g_pos[row] = v; g_pos[col] = v;
                            }
                        }
                }
                s += __shfl_xor_sync(0xFFFFFFFFu, s, 1);
                s += __shfl_xor_sync(0xFFFFFFFFu, s, 2);
                if ((lane & 3) == 0) atomicAdd(&g_rowsum[row], s);
            }
        }

        if (!diagW) {
#pragma unroll
            for (int ni = 0; ni < 8; ni++) {
                float2 cf = __half22float2(colsum2[ni]);
#pragma unroll
                for (int cc = 0; cc < 2; cc++) {
                    float s = cc ? cf.y : cf.x;
                    s += __shfl_xor_sync(0xFFFFFFFFu, s, 4);
                    s += __shfl_xor_sync(0xFFFFFFFFu, s, 8);
                    s += __shfl_xor_sync(0xFFFFFFFFu, s, 16);
                    if (lane < 4) {
                        int col = wc + ni * 8 + 2 * lane + cc;
                        atomicAdd(&g_rowsum[col], s);
                    }
                }
            }
        }
    }

    // ---- last-CTA finalize
    __threadfence();
    __syncthreads();
    __shared__ unsigned s_last;
    if (tid == 0) s_last = (atomicAdd(&g_done, 1u) == NT2 - 1) ? 1u : 0u;
    __syncthreads();
    if (s_last) {
        __shared__ float red[NTHR];
        float s = 0.0f;
        for (int i = tid; i < NTOT; i += NTHR)
            s += 2.0f + __logf(__ldcg(&g_rowsum[i])) - __ldcg(&g_pos[i]);
        red[tid] = s;
        __syncthreads();
#pragma unroll
        for (int o = NTHR / 2; o; o >>= 1) {
            if (tid < o) red[tid] += red[tid + o];
            __syncthreads();
        }
        if (tid == 0) out[0] = red[0] * (1.0f / NTOT);
    }
}

extern "C" void kernel_launch(void* const* d_in, const int* in_sizes, int n_in,
                              void* d_out, int out_size) {
    const float* zi = (const float*)d_in[0];
    const float* zj = (const float*)d_in[1];
    float* out = (float*)d_out;
    (void)in_sizes; (void)n_in; (void)out_size;

    cudaFuncSetAttribute(nt_mma, cudaFuncAttributeMaxDynamicSharedMemorySize, SMEM_TOTAL);

    nt_normalize<<<NTOT / 8, 256>>>(zi, zj);
    nt_mma<<<NT2, NTHR, SMEM_TOTAL>>>(out);
}